// round 15
// baseline (speedup 1.0000x reference)
#include <cuda_runtime.h>

#define BB 256
#define NN 400
#define DD 256
#define DEGC 32
#define EE (BB*NN*DEGC)        // 3276800
#define KK 200
#define NCC (NN-KK)            // 200
#define NT (BB*NN)             // 102400
#define BK (BB*KK)             // 51200
#define BC (BB*NCC)            // 51200
#define EQ4 (EE/4)             // 819200 int4 edge quads total

// output offsets (float32 elements)
#define OFF_DIS   ((size_t)0)
#define OFF_COM   ((size_t)BK*DD)                 // 13107200
#define OFF_PERM  (OFF_COM + (size_t)BC*DD)       // 26214400
#define OFF_PERMC (OFF_PERM + BK)                 // 26265600
#define OFF_SOFT  (OFF_PERMC + BC)                // 26316800
#define OFF_EDIS  (OFF_SOFT + NT)                 // 26419200
#define OFF_ECOM  (OFF_EDIS + EE)                 // 29696000

// Deterministic packed accumulator per node (global, L2 atomics):
//   bits [56:64) : deg_in count
//   bits [0:56)  : sum over edges of (llrint((double)h * 2^28) + 2^47)
#define AGG_SCALE 268435456.0           // 2^28
#define AGG_BIAS  (1ll << 47)
#define MASK56    ((1ull << 56) - 1ull)

__device__ unsigned long long g_acc[NT];      // zero at load; re-zeroed by k_topk
__device__ int    g_deg_out[NT];              // zero at load; re-zeroed by k_h
__device__ float  g_p[NT];
__device__ float  g_h[NT];
__device__ float  g_score[NT];
__device__ int    g_perm[BK];
__device__ int    g_permc[BC];
__device__ unsigned char g_sel[NT];
__device__ float  g_sumexp_part[BB];          // overwritten each launch

__device__ __forceinline__ unsigned enc_f(float f) {
    unsigned u = __float_as_uint(f);
    return (u >> 31) ? ~u : (u | 0x80000000u);
}

// FROZEN (score-producing): heterogeneous grid, 16000 blocks of 256 threads.
// 4-of-5 blocks do p = feat@W (warp per node), 1-of-5 do deg_out atomics.
// No grid-dep-sync: shares no buffers with the previous replay's k_final,
// so it may fully overlap its tail under PDL.
__global__ void __launch_bounds__(256) k_xw_deg(const float* __restrict__ feat,
                                                const float* __restrict__ W,
                                                const int* __restrict__ src) {
    int b = blockIdx.x;
    if ((b % 5) == 4) {
        int i = (b / 5) * 256 + threadIdx.x;   // [0, EE/4)
        int4 s = ((const int4*)src)[i];
        atomicAdd(&g_deg_out[s.x], 1); atomicAdd(&g_deg_out[s.y], 1);
        atomicAdd(&g_deg_out[s.z], 1); atomicAdd(&g_deg_out[s.w], 1);
        return;
    }
    __shared__ __align__(16) float sW[DD];
    int t = threadIdx.x;
    for (int i = t; i < DD; i += 256) sW[i] = W[i];
    __syncthreads();
    int chunk = (b / 5) * 4 + (b % 5);         // [0, 12800)
    int warp = t >> 5, lane = t & 31;
    int node = chunk * 8 + warp;
    const float4* f4 = (const float4*)(feat + (size_t)node * DD);
    const float4* w4 = (const float4*)sW;
    float acc = 0.f;
#pragma unroll
    for (int j = 0; j < 2; j++) {
        float4 v = f4[lane * 2 + j];
        float4 w = w4[lane * 2 + j];
        acc += v.x * w.x + v.y * w.y + v.z * w.z + v.w * w.w;
    }
#pragma unroll
    for (int o = 16; o > 0; o >>= 1) acc += __shfl_down_sync(0xffffffffu, acc, o);
    if (lane == 0) g_p[node] = acc;
}

// FROZEN: h = p * deg_out^-1/2; re-zeroes deg_out for the next replay.
__global__ void k_h() {
    cudaGridDependencySynchronize();
    int i = blockIdx.x * blockDim.x + threadIdx.x;
    if (i >= NT) return;
    int dg = g_deg_out[i];
    g_h[i] = g_p[i] * rsqrtf(fmaxf((float)dg, 1.f));
    g_deg_out[i] = 0;
}

__device__ __forceinline__ unsigned long long pack_edge(float h) {
    long long fixedv = llrint((double)h * AGG_SCALE);
    return (1ull << 56) + (unsigned long long)(fixedv + AGG_BIAS);
}

// Fused deg_in + agg, 16 edges per thread (MLP=16, 800 blocks = 1 wave).
__global__ void __launch_bounds__(256) k_agg(const int* __restrict__ src,
                                             const int* __restrict__ dst) {
    cudaGridDependencySynchronize();
    int i = blockIdx.x * blockDim.x + threadIdx.x;   // [0, EE/16)
    const int4* s4 = (const int4*)src;
    const int4* d4 = (const int4*)dst;
    int4 S0 = s4[i * 4],     S1 = s4[i * 4 + 1];
    int4 S2 = s4[i * 4 + 2], S3 = s4[i * 4 + 3];
    int4 D0 = d4[i * 4],     D1 = d4[i * 4 + 1];
    int4 D2 = d4[i * 4 + 2], D3 = d4[i * 4 + 3];
    float h0 = g_h[S0.x], h1 = g_h[S0.y], h2 = g_h[S0.z], h3 = g_h[S0.w];
    float h4 = g_h[S1.x], h5 = g_h[S1.y], h6 = g_h[S1.z], h7 = g_h[S1.w];
    float h8 = g_h[S2.x], h9 = g_h[S2.y], hA = g_h[S2.z], hB = g_h[S2.w];
    float hC = g_h[S3.x], hD = g_h[S3.y], hE = g_h[S3.z], hF = g_h[S3.w];
    atomicAdd(&g_acc[D0.x], pack_edge(h0));
    atomicAdd(&g_acc[D0.y], pack_edge(h1));
    atomicAdd(&g_acc[D0.z], pack_edge(h2));
    atomicAdd(&g_acc[D0.w], pack_edge(h3));
    atomicAdd(&g_acc[D1.x], pack_edge(h4));
    atomicAdd(&g_acc[D1.y], pack_edge(h5));
    atomicAdd(&g_acc[D1.z], pack_edge(h6));
    atomicAdd(&g_acc[D1.w], pack_edge(h7));
    atomicAdd(&g_acc[D2.x], pack_edge(h8));
    atomicAdd(&g_acc[D2.y], pack_edge(h9));
    atomicAdd(&g_acc[D2.z], pack_edge(hA));
    atomicAdd(&g_acc[D2.w], pack_edge(hB));
    atomicAdd(&g_acc[D3.x], pack_edge(hC));
    atomicAdd(&g_acc[D3.y], pack_edge(hD));
    atomicAdd(&g_acc[D3.z], pack_edge(hE));
    atomicAdd(&g_acc[D3.w], pack_edge(hF));
}

// One block (512 threads) per graph: frozen score decode + sum-exp partial +
// bitonic topk (proven form) + perm/permc + g_sel export. Re-zeroes g_acc.
__global__ void __launch_bounds__(512) k_topk(const float* __restrict__ bptr,
                                              float* __restrict__ out) {
    __shared__ unsigned long long keys[512];
    __shared__ int scan[512];
    __shared__ unsigned char flags[512];
    __shared__ float ssc[NN];
    __shared__ float sred[512];
    cudaGridDependencySynchronize();
    int g = blockIdx.x;
    int t = threadIdx.x;
    float b0 = bptr[0];

    float lsum = 0.f;
    if (t < NN) {
        unsigned long long v = g_acc[(size_t)g * NN + t];
        g_acc[(size_t)g * NN + t] = 0ull;
        unsigned C = (unsigned)(v >> 56);
        long long S = (long long)(v & MASK56);
        double agg = (double)(S - ((long long)C << 47)) * (1.0 / AGG_SCALE);
        float s = (float)agg * rsqrtf(fmaxf((float)C, 1.f)) + b0;
        ssc[t] = s;
        g_score[(size_t)g * NN + t] = s;
        lsum = expf(s);
    }
    sred[t] = lsum;
    __syncthreads();
    for (int o = 256; o > 0; o >>= 1) {
        if (t < o) sred[t] += sred[t + o];
        __syncthreads();
    }
    if (t == 0) g_sumexp_part[g] = sred[0];

    {
        unsigned long long key;
        if (t < NN) {
            unsigned u = enc_f(ssc[t]);
            key = (((unsigned long long)(~u)) << 32) | (unsigned)t;
        } else {
            key = 0xFFFFFFFFFFFFFFFFull;
        }
        keys[t] = key;
        flags[t] = 0;
    }
    __syncthreads();
    for (int k = 2; k <= 512; k <<= 1) {
        for (int j = k >> 1; j > 0; j >>= 1) {
            int ixj = t ^ j;
            if (ixj > t) {
                bool up = ((t & k) == 0);
                unsigned long long a = keys[t], c = keys[ixj];
                if ((a > c) == up) { keys[t] = c; keys[ixj] = a; }
            }
            __syncthreads();
        }
    }
    if (t < KK) {
        int local = (int)(keys[t] & 0xffffffffu);
        flags[local] = 1;
        int gid = g * NN + local;
        g_perm[g * KK + t] = gid;
        out[OFF_PERM + (size_t)g * KK + t] = (float)gid;
    }
    __syncthreads();
    if (t < NN) g_sel[g * NN + t] = flags[t];
    scan[t] = (t < NN && !flags[t]) ? 1 : 0;
    __syncthreads();
    for (int off = 1; off < 512; off <<= 1) {
        int add = (t >= off) ? scan[t - off] : 0;
        __syncthreads();
        scan[t] += add;
        __syncthreads();
    }
    if (t < NN && !flags[t]) {
        int p = scan[t] - 1;
        int gid = g * NN + t;
        g_permc[g * NCC + p] = gid;
        out[OFF_PERMC + (size_t)g * NCC + p] = (float)gid;
    }
}

// Heterogeneous final kernel, 4800 blocks of 512 threads:
//   2-of-3 blocks (3200): gated gather + softmax, 32 rows/block, 2 rows/warp
//                         (4 independent float4 loads per thread = MLP 4)
//   1-of-3 blocks (1600): edge masks (one int4 quad per thread)
__global__ void __launch_bounds__(512) k_final(const float* __restrict__ feat,
                                               const int* __restrict__ src,
                                               const int* __restrict__ dst,
                                               float* __restrict__ out) {
    cudaGridDependencySynchronize();
    int b = blockIdx.x;
    int t = threadIdx.x;
    if ((b % 3) == 2) {
        int i = (b / 3) * 512 + t;             // [0, EQ4)
        int4 s = __ldcs(&((const int4*)src)[i]);
        int4 d = __ldcs(&((const int4*)dst)[i]);
        unsigned char sx = g_sel[s.x], sy = g_sel[s.y];
        unsigned char sz = g_sel[s.z], sw = g_sel[s.w];
        unsigned char dx = g_sel[d.x], dy = g_sel[d.y];
        unsigned char dz = g_sel[d.z], dw = g_sel[d.w];
        float4 dis, com;
        dis.x = (sx & dx) ? 1.f : 0.f;  com.x = (!sx && !dx) ? 1.f : 0.f;
        dis.y = (sy & dy) ? 1.f : 0.f;  com.y = (!sy && !dy) ? 1.f : 0.f;
        dis.z = (sz & dz) ? 1.f : 0.f;  com.z = (!sz && !dz) ? 1.f : 0.f;
        dis.w = (sw & dw) ? 1.f : 0.f;  com.w = (!sw && !dw) ? 1.f : 0.f;
        __stcs(&((float4*)(out + OFF_EDIS))[i], dis);
        __stcs(&((float4*)(out + OFF_ECOM))[i], com);
        return;
    }
    __shared__ float ssum;
    if (t < 32) {
        float a = 0.f;
#pragma unroll
        for (int j = 0; j < 8; j++) a += g_sumexp_part[t * 8 + j];
#pragma unroll
        for (int o = 16; o > 0; o >>= 1) a += __shfl_down_sync(0xffffffffu, a, o);
        if (t == 0) ssum = a;
    }
    __syncthreads();
    float denom = ssum;

    int ord = (b / 3) * 2 + (b % 3);          // [0, 3200)
    int warp = t >> 5, lane = t & 31;
    long rowA = (long)ord * 32 + warp * 2;    // 32 rows/block, 2 per warp
    long rowB = rowA + 1;
    int nodeA, nodeB; size_t oA, oB;
    if (rowA < BK) { nodeA = g_perm[rowA]; oA = OFF_DIS + (size_t)rowA * DD; }
    else { long r2 = rowA - BK; nodeA = g_permc[r2]; oA = OFF_COM + (size_t)r2 * DD; }
    if (rowB < BK) { nodeB = g_perm[rowB]; oB = OFF_DIS + (size_t)rowB * DD; }
    else { long r2 = rowB - BK; nodeB = g_permc[r2]; oB = OFF_COM + (size_t)r2 * DD; }
    float scA = g_score[nodeA], scB = g_score[nodeB];
    float gA = tanhf(scA), gB = tanhf(scB);
    const float4* fA = (const float4*)(feat + (size_t)nodeA * DD);
    const float4* fB = (const float4*)(feat + (size_t)nodeB * DD);
    float4 a0 = __ldcs(&fA[lane]);
    float4 a1 = __ldcs(&fA[lane + 32]);
    float4 c0 = __ldcs(&fB[lane]);
    float4 c1 = __ldcs(&fB[lane + 32]);
    a0.x *= gA; a0.y *= gA; a0.z *= gA; a0.w *= gA;
    a1.x *= gA; a1.y *= gA; a1.z *= gA; a1.w *= gA;
    c0.x *= gB; c0.y *= gB; c0.z *= gB; c0.w *= gB;
    c1.x *= gB; c1.y *= gB; c1.z *= gB; c1.w *= gB;
    float4* pA = (float4*)(out + oA);
    float4* pB = (float4*)(out + oB);
    __stcs(&pA[lane], a0);
    __stcs(&pA[lane + 32], a1);
    __stcs(&pB[lane], c0);
    __stcs(&pB[lane + 32], c1);
    if (lane == 0) {
        out[OFF_SOFT + nodeA] = expf(scA) / denom;
        out[OFF_SOFT + nodeB] = expf(scB) / denom;
    }
}

// PDL launch helper: dependent blocks spin up during the predecessor's tail.
template <typename F, typename... Args>
static void launch_pdl(F f, dim3 grid, dim3 block, Args... args) {
    cudaLaunchConfig_t cfg = {};
    cfg.gridDim = grid;
    cfg.blockDim = block;
    cfg.stream = 0;
    cudaLaunchAttribute at[1];
    at[0].id = cudaLaunchAttributeProgrammaticStreamSerialization;
    at[0].val.programmaticStreamSerializationAllowed = 1;
    cfg.attrs = at;
    cfg.numAttrs = 1;
    cudaLaunchKernelEx(&cfg, f, args...);
}

extern "C" void kernel_launch(void* const* d_in, const int* in_sizes, int n_in,
                              void* d_out, int out_size) {
    const float* feat = (const float*)d_in[0];
    const float* W    = (const float*)d_in[1];
    const float* b    = (const float*)d_in[2];
    const int*   src  = (const int*)d_in[3];
    const int*   dst  = (const int*)d_in[4];
    float* out = (float*)d_out;
    (void)in_sizes; (void)n_in; (void)out_size;

    // xw_deg gets PDL too: it shares no buffers with the previous replay's
    // k_final, so in the timed graph loop it overlaps that kernel's tail.
    launch_pdl(k_xw_deg, dim3(16000), dim3(256), feat, W, src);
    launch_pdl(k_h, dim3(NT / 256), dim3(256));
    launch_pdl(k_agg, dim3(EE / 16 / 256), dim3(256), src, dst);
    launch_pdl(k_topk, dim3(BB), dim3(512), b, out);
    launch_pdl(k_final, dim3(4800), dim3(512), feat, src, dst, out);
}

// round 16
// speedup vs baseline: 1.0223x; 1.0223x over previous
#include <cuda_runtime.h>

#define BB 256
#define NN 400
#define DD 256
#define DEGC 32
#define EE (BB*NN*DEGC)        // 3276800
#define KK 200
#define NCC (NN-KK)            // 200
#define NT (BB*NN)             // 102400
#define BK (BB*KK)             // 51200
#define BC (BB*NCC)            // 51200
#define EQ4 (EE/4)             // 819200 int4 edge quads total

// output offsets (float32 elements)
#define OFF_DIS   ((size_t)0)
#define OFF_COM   ((size_t)BK*DD)                 // 13107200
#define OFF_PERM  (OFF_COM + (size_t)BC*DD)       // 26214400
#define OFF_PERMC (OFF_PERM + BK)                 // 26265600
#define OFF_SOFT  (OFF_PERMC + BC)                // 26316800
#define OFF_EDIS  (OFF_SOFT + NT)                 // 26419200
#define OFF_ECOM  (OFF_EDIS + EE)                 // 29696000

// Deterministic packed accumulator per node (global, L2 atomics):
//   bits [56:64) : deg_in count
//   bits [0:56)  : sum over edges of (llrint((double)h * 2^28) + 2^47)
#define AGG_SCALE 268435456.0           // 2^28
#define AGG_BIAS  (1ll << 47)
#define MASK56    ((1ull << 56) - 1ull)

__device__ unsigned long long g_acc[NT];      // zero at load; re-zeroed by k_topk
__device__ int    g_deg_out[NT];              // zero at load; re-zeroed by k_h
__device__ float  g_p[NT];
__device__ float  g_h[NT];
__device__ float  g_score[NT];
__device__ int    g_perm[BK];
__device__ int    g_permc[BC];
__device__ unsigned char g_sel[NT];
__device__ float  g_sumexp_part[BB];          // overwritten each launch

__device__ __forceinline__ unsigned enc_f(float f) {
    unsigned u = __float_as_uint(f);
    return (u >> 31) ? ~u : (u | 0x80000000u);
}

// FROZEN (score-producing): heterogeneous grid, 16000 blocks of 256 threads.
__global__ void __launch_bounds__(256) k_xw_deg(const float* __restrict__ feat,
                                                const float* __restrict__ W,
                                                const int* __restrict__ src) {
    int b = blockIdx.x;
    if ((b % 5) == 4) {
        int i = (b / 5) * 256 + threadIdx.x;   // [0, EE/4)
        int4 s = ((const int4*)src)[i];
        atomicAdd(&g_deg_out[s.x], 1); atomicAdd(&g_deg_out[s.y], 1);
        atomicAdd(&g_deg_out[s.z], 1); atomicAdd(&g_deg_out[s.w], 1);
        return;
    }
    __shared__ __align__(16) float sW[DD];
    int t = threadIdx.x;
    for (int i = t; i < DD; i += 256) sW[i] = W[i];
    __syncthreads();
    int chunk = (b / 5) * 4 + (b % 5);         // [0, 12800)
    int warp = t >> 5, lane = t & 31;
    int node = chunk * 8 + warp;
    const float4* f4 = (const float4*)(feat + (size_t)node * DD);
    const float4* w4 = (const float4*)sW;
    float acc = 0.f;
#pragma unroll
    for (int j = 0; j < 2; j++) {
        float4 v = f4[lane * 2 + j];
        float4 w = w4[lane * 2 + j];
        acc += v.x * w.x + v.y * w.y + v.z * w.z + v.w * w.w;
    }
#pragma unroll
    for (int o = 16; o > 0; o >>= 1) acc += __shfl_down_sync(0xffffffffu, acc, o);
    if (lane == 0) g_p[node] = acc;
}

// FROZEN: h = p * deg_out^-1/2; re-zeroes deg_out for the next replay.
__global__ void k_h() {
    cudaGridDependencySynchronize();
    int i = blockIdx.x * blockDim.x + threadIdx.x;
    if (i >= NT) return;
    int dg = g_deg_out[i];
    g_h[i] = g_p[i] * rsqrtf(fmaxf((float)dg, 1.f));
    g_deg_out[i] = 0;
}

__device__ __forceinline__ unsigned long long pack_edge(float h) {
    long long fixedv = llrint((double)h * AGG_SCALE);
    return (1ull << 56) + (unsigned long long)(fixedv + AGG_BIAS);
}

// Fused deg_in + agg, 16 edges per thread (MLP=16, 800 blocks = 1 wave).
__global__ void __launch_bounds__(256) k_agg(const int* __restrict__ src,
                                             const int* __restrict__ dst) {
    cudaGridDependencySynchronize();
    int i = blockIdx.x * blockDim.x + threadIdx.x;   // [0, EE/16)
    const int4* s4 = (const int4*)src;
    const int4* d4 = (const int4*)dst;
    int4 S0 = s4[i * 4],     S1 = s4[i * 4 + 1];
    int4 S2 = s4[i * 4 + 2], S3 = s4[i * 4 + 3];
    int4 D0 = d4[i * 4],     D1 = d4[i * 4 + 1];
    int4 D2 = d4[i * 4 + 2], D3 = d4[i * 4 + 3];
    float h0 = g_h[S0.x], h1 = g_h[S0.y], h2 = g_h[S0.z], h3 = g_h[S0.w];
    float h4 = g_h[S1.x], h5 = g_h[S1.y], h6 = g_h[S1.z], h7 = g_h[S1.w];
    float h8 = g_h[S2.x], h9 = g_h[S2.y], hA = g_h[S2.z], hB = g_h[S2.w];
    float hC = g_h[S3.x], hD = g_h[S3.y], hE = g_h[S3.z], hF = g_h[S3.w];
    atomicAdd(&g_acc[D0.x], pack_edge(h0));
    atomicAdd(&g_acc[D0.y], pack_edge(h1));
    atomicAdd(&g_acc[D0.z], pack_edge(h2));
    atomicAdd(&g_acc[D0.w], pack_edge(h3));
    atomicAdd(&g_acc[D1.x], pack_edge(h4));
    atomicAdd(&g_acc[D1.y], pack_edge(h5));
    atomicAdd(&g_acc[D1.z], pack_edge(h6));
    atomicAdd(&g_acc[D1.w], pack_edge(h7));
    atomicAdd(&g_acc[D2.x], pack_edge(h8));
    atomicAdd(&g_acc[D2.y], pack_edge(h9));
    atomicAdd(&g_acc[D2.z], pack_edge(hA));
    atomicAdd(&g_acc[D2.w], pack_edge(hB));
    atomicAdd(&g_acc[D3.x], pack_edge(hC));
    atomicAdd(&g_acc[D3.y], pack_edge(hD));
    atomicAdd(&g_acc[D3.z], pack_edge(hE));
    atomicAdd(&g_acc[D3.w], pack_edge(hF));
}

// One block (512 threads) per graph. Frozen score decode. Register-resident
// bitonic sort: intra-warp rounds (j<32) via shfl_xor (no barriers), cross-
// warp rounds (j>=32) via smem. Correct sorting network on the same unique
// keys -> identical permutation as before. Ballot-based complement (R13-
// proven logic). Re-zeroes g_acc for the next replay.
__global__ void __launch_bounds__(512) k_topk(const float* __restrict__ bptr,
                                              float* __restrict__ out) {
    __shared__ unsigned long long skey[512];
    __shared__ float sred[16];
    __shared__ unsigned char flags[512];
    __shared__ unsigned swords[16];
    __shared__ int wpref[16];
    cudaGridDependencySynchronize();
    int g = blockIdx.x;
    int t = threadIdx.x;
    int warp = t >> 5, lane = t & 31;
    float b0 = bptr[0];

    // decode scores (frozen arithmetic); build key; local exp term
    unsigned long long key = 0xFFFFFFFFFFFFFFFFull;
    float ex = 0.f;
    if (t < NN) {
        unsigned long long v = g_acc[(size_t)g * NN + t];
        g_acc[(size_t)g * NN + t] = 0ull;
        unsigned C = (unsigned)(v >> 56);
        long long S = (long long)(v & MASK56);
        double agg = (double)(S - ((long long)C << 47)) * (1.0 / AGG_SCALE);
        float s = (float)agg * rsqrtf(fmaxf((float)C, 1.f)) + b0;
        g_score[(size_t)g * NN + t] = s;
        key = (((unsigned long long)(~enc_f(s))) << 32) | (unsigned)t;
        ex = expf(s);
    }
    // sum-exp: warp shuffle reduce, then warp 0 combines 16 partials
#pragma unroll
    for (int o = 16; o > 0; o >>= 1) ex += __shfl_down_sync(0xffffffffu, ex, o);
    if (lane == 0) sred[warp] = ex;
    flags[t] = 0;
    __syncthreads();
    if (t < 32) {
        float a = (t < 16) ? sred[t] : 0.f;
#pragma unroll
        for (int o = 8; o > 0; o >>= 1) a += __shfl_down_sync(0xffffffffu, a, o);
        if (t == 0) g_sumexp_part[g] = a;
    }

    // bitonic sort, key in register
#pragma unroll
    for (int k = 2; k <= 512; k <<= 1) {
        for (int j = k >> 1; j > 0; j >>= 1) {
            bool up = ((t & k) == 0);
            bool lower = ((t & j) == 0);
            unsigned long long pk;
            if (j >= 32) {
                skey[t] = key;
                __syncthreads();
                pk = skey[t ^ j];
                __syncthreads();
            } else {
                pk = __shfl_xor_sync(0xffffffffu, key, j);
            }
            bool takeMin = (lower == up);
            unsigned long long mn = key < pk ? key : pk;
            unsigned long long mx = key < pk ? pk : key;
            key = takeMin ? mn : mx;
        }
    }
    // thread t holds the rank-t key (ascending = score desc, idx asc)
    if (t < KK) {
        int local = (int)(key & 0xffffffffu);
        flags[local] = 1;
        int gid = g * NN + local;
        g_perm[g * KK + t] = gid;
        out[OFF_PERM + (size_t)g * KK + t] = (float)gid;
    }
    __syncthreads();

    bool selflag = (t < NN) && flags[t];
    int gid = g * NN + t;
    unsigned bal = __ballot_sync(0xffffffffu, selflag);
    if (lane == 0) swords[warp] = bal;
    __syncthreads();
    if (t < 32) {
        int v = (t < 16) ? __popc(swords[t]) : 0;
        int inc = v;
#pragma unroll
        for (int o = 1; o < 32; o <<= 1) {
            int up2 = __shfl_up_sync(0xffffffffu, inc, o);
            if (lane >= o) inc += up2;
        }
        if (t < 16) wpref[t] = inc - v;        // exclusive prefix over warps
    }
    __syncthreads();
    if (t < NN) {
        g_sel[gid] = selflag ? 1 : 0;
        if (!selflag) {
            int selbefore = wpref[warp] + __popc(swords[warp] & ((1u << lane) - 1u));
            int p = t - selbefore;             // position among unselected, idx asc
            g_permc[g * NCC + p] = gid;
            out[OFF_PERMC + (size_t)g * NCC + p] = (float)gid;
        }
    }
}

// Heterogeneous final kernel (R14-proven shape), 8000 blocks of 512 threads:
//   4-of-5 blocks (6400): gated gather + softmax (16 rows x 32 lanes, MLP=2)
//   1-of-5 blocks (1600): edge masks (one int4 quad per thread)
__global__ void __launch_bounds__(512) k_final(const float* __restrict__ feat,
                                               const int* __restrict__ src,
                                               const int* __restrict__ dst,
                                               float* __restrict__ out) {
    cudaGridDependencySynchronize();
    int b = blockIdx.x;
    int t = threadIdx.x;
    if ((b % 5) == 4) {
        int i = (b / 5) * 512 + t;             // [0, EQ4)
        int4 s = __ldcs(&((const int4*)src)[i]);
        int4 d = __ldcs(&((const int4*)dst)[i]);
        unsigned char sx = g_sel[s.x], sy = g_sel[s.y];
        unsigned char sz = g_sel[s.z], sw = g_sel[s.w];
        unsigned char dx = g_sel[d.x], dy = g_sel[d.y];
        unsigned char dz = g_sel[d.z], dw = g_sel[d.w];
        float4 dis, com;
        dis.x = (sx & dx) ? 1.f : 0.f;  com.x = (!sx && !dx) ? 1.f : 0.f;
        dis.y = (sy & dy) ? 1.f : 0.f;  com.y = (!sy && !dy) ? 1.f : 0.f;
        dis.z = (sz & dz) ? 1.f : 0.f;  com.z = (!sz && !dz) ? 1.f : 0.f;
        dis.w = (sw & dw) ? 1.f : 0.f;  com.w = (!sw && !dw) ? 1.f : 0.f;
        __stcs(&((float4*)(out + OFF_EDIS))[i], dis);
        __stcs(&((float4*)(out + OFF_ECOM))[i], com);
        return;
    }
    __shared__ float ssum;
    if (t < 32) {
        float a = 0.f;
#pragma unroll
        for (int j = 0; j < 8; j++) a += g_sumexp_part[t * 8 + j];
#pragma unroll
        for (int o = 16; o > 0; o >>= 1) a += __shfl_down_sync(0xffffffffu, a, o);
        if (t == 0) ssum = a;
    }
    __syncthreads();
    float denom = ssum;

    int ord = (b / 5) * 4 + (b % 5);          // [0, 6400)
    int rowInBlk = t >> 5;                    // 16 rows per block
    int lane = t & 31;
    long row = (long)ord * 16 + rowInBlk;
    int node; size_t obase;
    if (row < BK) {
        node = g_perm[row];
        obase = OFF_DIS + (size_t)row * DD;
    } else {
        long r2 = row - BK;
        node = g_permc[r2];
        obase = OFF_COM + (size_t)r2 * DD;
    }
    float sc = g_score[node];
    float gate = tanhf(sc);
    const float4* f4 = (const float4*)(feat + (size_t)node * DD);
    float4* o4 = (float4*)(out + obase);
    float4 v0 = __ldcs(&f4[lane]);
    float4 v1 = __ldcs(&f4[lane + 32]);
    v0.x *= gate; v0.y *= gate; v0.z *= gate; v0.w *= gate;
    v1.x *= gate; v1.y *= gate; v1.z *= gate; v1.w *= gate;
    __stcs(&o4[lane], v0);
    __stcs(&o4[lane + 32], v1);
    if (lane == 0) out[OFF_SOFT + node] = expf(sc) / denom;
}

// PDL launch helper: dependent blocks spin up during the predecessor's tail.
template <typename F, typename... Args>
static void launch_pdl(F f, dim3 grid, dim3 block, Args... args) {
    cudaLaunchConfig_t cfg = {};
    cfg.gridDim = grid;
    cfg.blockDim = block;
    cfg.stream = 0;
    cudaLaunchAttribute at[1];
    at[0].id = cudaLaunchAttributeProgrammaticStreamSerialization;
    at[0].val.programmaticStreamSerializationAllowed = 1;
    cfg.attrs = at;
    cfg.numAttrs = 1;
    cudaLaunchKernelEx(&cfg, f, args...);
}

extern "C" void kernel_launch(void* const* d_in, const int* in_sizes, int n_in,
                              void* d_out, int out_size) {
    const float* feat = (const float*)d_in[0];
    const float* W    = (const float*)d_in[1];
    const float* b    = (const float*)d_in[2];
    const int*   src  = (const int*)d_in[3];
    const int*   dst  = (const int*)d_in[4];
    float* out = (float*)d_out;
    (void)in_sizes; (void)n_in; (void)out_size;

    launch_pdl(k_xw_deg, dim3(16000), dim3(256), feat, W, src);
    launch_pdl(k_h, dim3(NT / 256), dim3(256));
    launch_pdl(k_agg, dim3(EE / 16 / 256), dim3(256), src, dst);
    launch_pdl(k_topk, dim3(BB), dim3(512), b, out);
    launch_pdl(k_final, dim3(8000), dim3(512), feat, src, dst, out);
}

// round 17
// speedup vs baseline: 1.0583x; 1.0352x over previous
#include <cuda_runtime.h>

#define BB 256
#define NN 400
#define DD 256
#define DEGC 32
#define EE (BB*NN*DEGC)        // 3276800
#define KK 200
#define NCC (NN-KK)            // 200
#define NT (BB*NN)             // 102400
#define BK (BB*KK)             // 51200
#define BC (BB*NCC)            // 51200
#define EQ4 (EE/4)             // 819200 int4 edge quads total

// output offsets (float32 elements)
#define OFF_DIS   ((size_t)0)
#define OFF_COM   ((size_t)BK*DD)                 // 13107200 == BK*DD (contiguous!)
#define OFF_PERM  (OFF_COM + (size_t)BC*DD)       // 26214400
#define OFF_PERMC (OFF_PERM + BK)                 // 26265600
#define OFF_SOFT  (OFF_PERMC + BC)                // 26316800
#define OFF_EDIS  (OFF_SOFT + NT)                 // 26419200
#define OFF_ECOM  (OFF_EDIS + EE)                 // 29696000

// Deterministic packed accumulator per node (global, L2 atomics):
//   bits [56:64) : deg_in count
//   bits [0:56)  : sum over edges of (llrint((double)h * 2^28) + 2^47)
#define AGG_SCALE 268435456.0           // 2^28
#define AGG_BIAS  (1ll << 47)
#define MASK56    ((1ull << 56) - 1ull)

__device__ unsigned long long g_acc[NT];      // zero at load; re-zeroed by k_topk
__device__ int    g_deg_out[NT];              // zero at load; re-zeroed by k_h
__device__ float  g_p[NT];
__device__ float  g_h[NT];
__device__ float  g_score[NT];
__device__ int    g_dest[NT];                 // node -> output row (dis rows then com rows)
__device__ unsigned char g_sel[NT];
__device__ float  g_sumexp_part[BB];          // overwritten each launch

__device__ __forceinline__ unsigned enc_f(float f) {
    unsigned u = __float_as_uint(f);
    return (u >> 31) ? ~u : (u | 0x80000000u);
}

// FROZEN (score-producing): heterogeneous grid, 16000 blocks of 256 threads.
__global__ void __launch_bounds__(256) k_xw_deg(const float* __restrict__ feat,
                                                const float* __restrict__ W,
                                                const int* __restrict__ src) {
    int b = blockIdx.x;
    if ((b % 5) == 4) {
        int i = (b / 5) * 256 + threadIdx.x;   // [0, EE/4)
        int4 s = ((const int4*)src)[i];
        atomicAdd(&g_deg_out[s.x], 1); atomicAdd(&g_deg_out[s.y], 1);
        atomicAdd(&g_deg_out[s.z], 1); atomicAdd(&g_deg_out[s.w], 1);
        return;
    }
    __shared__ __align__(16) float sW[DD];
    int t = threadIdx.x;
    for (int i = t; i < DD; i += 256) sW[i] = W[i];
    __syncthreads();
    int chunk = (b / 5) * 4 + (b % 5);         // [0, 12800)
    int warp = t >> 5, lane = t & 31;
    int node = chunk * 8 + warp;
    const float4* f4 = (const float4*)(feat + (size_t)node * DD);
    const float4* w4 = (const float4*)sW;
    float acc = 0.f;
#pragma unroll
    for (int j = 0; j < 2; j++) {
        float4 v = f4[lane * 2 + j];
        float4 w = w4[lane * 2 + j];
        acc += v.x * w.x + v.y * w.y + v.z * w.z + v.w * w.w;
    }
#pragma unroll
    for (int o = 16; o > 0; o >>= 1) acc += __shfl_down_sync(0xffffffffu, acc, o);
    if (lane == 0) g_p[node] = acc;
}

// FROZEN: h = p * deg_out^-1/2; re-zeroes deg_out for the next replay.
__global__ void k_h() {
    cudaGridDependencySynchronize();
    int i = blockIdx.x * blockDim.x + threadIdx.x;
    if (i >= NT) return;
    int dg = g_deg_out[i];
    g_h[i] = g_p[i] * rsqrtf(fmaxf((float)dg, 1.f));
    g_deg_out[i] = 0;
}

__device__ __forceinline__ unsigned long long pack_edge(float h) {
    long long fixedv = llrint((double)h * AGG_SCALE);
    return (1ull << 56) + (unsigned long long)(fixedv + AGG_BIAS);
}

// Fused deg_in + agg, 16 edges per thread (MLP=16, 800 blocks = 1 wave).
__global__ void __launch_bounds__(256) k_agg(const int* __restrict__ src,
                                             const int* __restrict__ dst) {
    cudaGridDependencySynchronize();
    int i = blockIdx.x * blockDim.x + threadIdx.x;   // [0, EE/16)
    const int4* s4 = (const int4*)src;
    const int4* d4 = (const int4*)dst;
    int4 S0 = s4[i * 4],     S1 = s4[i * 4 + 1];
    int4 S2 = s4[i * 4 + 2], S3 = s4[i * 4 + 3];
    int4 D0 = d4[i * 4],     D1 = d4[i * 4 + 1];
    int4 D2 = d4[i * 4 + 2], D3 = d4[i * 4 + 3];
    float h0 = g_h[S0.x], h1 = g_h[S0.y], h2 = g_h[S0.z], h3 = g_h[S0.w];
    float h4 = g_h[S1.x], h5 = g_h[S1.y], h6 = g_h[S1.z], h7 = g_h[S1.w];
    float h8 = g_h[S2.x], h9 = g_h[S2.y], hA = g_h[S2.z], hB = g_h[S2.w];
    float hC = g_h[S3.x], hD = g_h[S3.y], hE = g_h[S3.z], hF = g_h[S3.w];
    atomicAdd(&g_acc[D0.x], pack_edge(h0));
    atomicAdd(&g_acc[D0.y], pack_edge(h1));
    atomicAdd(&g_acc[D0.z], pack_edge(h2));
    atomicAdd(&g_acc[D0.w], pack_edge(h3));
    atomicAdd(&g_acc[D1.x], pack_edge(h4));
    atomicAdd(&g_acc[D1.y], pack_edge(h5));
    atomicAdd(&g_acc[D1.z], pack_edge(h6));
    atomicAdd(&g_acc[D1.w], pack_edge(h7));
    atomicAdd(&g_acc[D2.x], pack_edge(h8));
    atomicAdd(&g_acc[D2.y], pack_edge(h9));
    atomicAdd(&g_acc[D2.z], pack_edge(hA));
    atomicAdd(&g_acc[D2.w], pack_edge(hB));
    atomicAdd(&g_acc[D3.x], pack_edge(hC));
    atomicAdd(&g_acc[D3.y], pack_edge(hD));
    atomicAdd(&g_acc[D3.z], pack_edge(hE));
    atomicAdd(&g_acc[D3.w], pack_edge(hF));
}

// One block (512 threads) per graph. Frozen score decode. Register-resident
// bitonic (R16-proven). Emits perm/permc outputs directly, g_sel for masks,
// and g_dest: node -> output row (uniform addressing, dis rows then com).
__global__ void __launch_bounds__(512) k_topk(const float* __restrict__ bptr,
                                              float* __restrict__ out) {
    __shared__ unsigned long long skey[512];
    __shared__ float sred[16];
    __shared__ unsigned char flags[512];
    __shared__ unsigned swords[16];
    __shared__ int wpref[16];
    cudaGridDependencySynchronize();
    int g = blockIdx.x;
    int t = threadIdx.x;
    int warp = t >> 5, lane = t & 31;
    float b0 = bptr[0];

    unsigned long long key = 0xFFFFFFFFFFFFFFFFull;
    float ex = 0.f;
    if (t < NN) {
        unsigned long long v = g_acc[(size_t)g * NN + t];
        g_acc[(size_t)g * NN + t] = 0ull;
        unsigned C = (unsigned)(v >> 56);
        long long S = (long long)(v & MASK56);
        double agg = (double)(S - ((long long)C << 47)) * (1.0 / AGG_SCALE);
        float s = (float)agg * rsqrtf(fmaxf((float)C, 1.f)) + b0;
        g_score[(size_t)g * NN + t] = s;
        key = (((unsigned long long)(~enc_f(s))) << 32) | (unsigned)t;
        ex = expf(s);
    }
#pragma unroll
    for (int o = 16; o > 0; o >>= 1) ex += __shfl_down_sync(0xffffffffu, ex, o);
    if (lane == 0) sred[warp] = ex;
    flags[t] = 0;
    __syncthreads();
    if (t < 32) {
        float a = (t < 16) ? sred[t] : 0.f;
#pragma unroll
        for (int o = 8; o > 0; o >>= 1) a += __shfl_down_sync(0xffffffffu, a, o);
        if (t == 0) g_sumexp_part[g] = a;
    }

    // register-resident bitonic sort (R16-proven network)
#pragma unroll
    for (int k = 2; k <= 512; k <<= 1) {
        for (int j = k >> 1; j > 0; j >>= 1) {
            bool up = ((t & k) == 0);
            bool lower = ((t & j) == 0);
            unsigned long long pk;
            if (j >= 32) {
                skey[t] = key;
                __syncthreads();
                pk = skey[t ^ j];
                __syncthreads();
            } else {
                pk = __shfl_xor_sync(0xffffffffu, key, j);
            }
            bool takeMin = (lower == up);
            unsigned long long mn = key < pk ? key : pk;
            unsigned long long mx = key < pk ? pk : key;
            key = takeMin ? mn : mx;
        }
    }
    // thread t holds the rank-t key (ascending = score desc, idx asc)
    if (t < KK) {
        int local = (int)(key & 0xffffffffu);
        flags[local] = 1;
        int gid = g * NN + local;
        g_dest[gid] = g * KK + t;                  // dis row
        out[OFF_PERM + (size_t)g * KK + t] = (float)gid;
    }
    __syncthreads();

    bool selflag = (t < NN) && flags[t];
    int gid = g * NN + t;
    unsigned bal = __ballot_sync(0xffffffffu, selflag);
    if (lane == 0) swords[warp] = bal;
    __syncthreads();
    if (t < 32) {
        int v = (t < 16) ? __popc(swords[t]) : 0;
        int inc = v;
#pragma unroll
        for (int o = 1; o < 32; o <<= 1) {
            int up2 = __shfl_up_sync(0xffffffffu, inc, o);
            if (lane >= o) inc += up2;
        }
        if (t < 16) wpref[t] = inc - v;            // exclusive prefix over warps
    }
    __syncthreads();
    if (t < NN) {
        g_sel[gid] = selflag ? 1 : 0;
        if (!selflag) {
            int selbefore = wpref[warp] + __popc(swords[warp] & ((1u << lane) - 1u));
            int p = t - selbefore;                 // position among unselected
            g_dest[gid] = BK + g * NCC + p;        // com row (uniform addressing)
            out[OFF_PERMC + (size_t)g * NCC + p] = (float)gid;
        }
    }
}

// Heterogeneous final kernel, 8000 blocks of 512 threads:
//   4-of-5 blocks (6400): gather in NODE order — sequential feat/score/dest
//     reads (streaming), random-but-contiguous 1KB row STORES (no latency).
//   1-of-5 blocks (1600): edge masks (one int4 quad per thread)
__global__ void __launch_bounds__(512) k_final(const float* __restrict__ feat,
                                               const int* __restrict__ src,
                                               const int* __restrict__ dst,
                                               float* __restrict__ out) {
    cudaGridDependencySynchronize();
    int b = blockIdx.x;
    int t = threadIdx.x;
    if ((b % 5) == 4) {
        int i = (b / 5) * 512 + t;             // [0, EQ4)
        int4 s = __ldcs(&((const int4*)src)[i]);
        int4 d = __ldcs(&((const int4*)dst)[i]);
        unsigned char sx = g_sel[s.x], sy = g_sel[s.y];
        unsigned char sz = g_sel[s.z], sw = g_sel[s.w];
        unsigned char dx = g_sel[d.x], dy = g_sel[d.y];
        unsigned char dz = g_sel[d.z], dw = g_sel[d.w];
        float4 dis, com;
        dis.x = (sx & dx) ? 1.f : 0.f;  com.x = (!sx && !dx) ? 1.f : 0.f;
        dis.y = (sy & dy) ? 1.f : 0.f;  com.y = (!sy && !dy) ? 1.f : 0.f;
        dis.z = (sz & dz) ? 1.f : 0.f;  com.z = (!sz && !dz) ? 1.f : 0.f;
        dis.w = (sw & dw) ? 1.f : 0.f;  com.w = (!sw && !dw) ? 1.f : 0.f;
        __stcs(&((float4*)(out + OFF_EDIS))[i], dis);
        __stcs(&((float4*)(out + OFF_ECOM))[i], com);
        return;
    }
    __shared__ float ssum;
    if (t < 32) {
        float a = 0.f;
#pragma unroll
        for (int j = 0; j < 8; j++) a += g_sumexp_part[t * 8 + j];
#pragma unroll
        for (int o = 16; o > 0; o >>= 1) a += __shfl_down_sync(0xffffffffu, a, o);
        if (t == 0) ssum = a;
    }
    __syncthreads();
    float denom = ssum;

    int ord = (b / 5) * 4 + (b % 5);          // [0, 6400)
    int nodeInBlk = t >> 5;                   // 16 consecutive nodes per block
    int lane = t & 31;
    int node = ord * 16 + nodeInBlk;          // sequential across the grid
    int dest = g_dest[node];                  // output row (dis rows then com)
    float sc = g_score[node];
    float gate = tanhf(sc);
    const float4* f4 = (const float4*)(feat + (size_t)node * DD);
    float4* o4 = (float4*)(out + (size_t)dest * DD);
    float4 v0 = __ldcs(&f4[lane]);
    float4 v1 = __ldcs(&f4[lane + 32]);
    v0.x *= gate; v0.y *= gate; v0.z *= gate; v0.w *= gate;
    v1.x *= gate; v1.y *= gate; v1.z *= gate; v1.w *= gate;
    __stcs(&o4[lane], v0);
    __stcs(&o4[lane + 32], v1);
    if (lane == 0) out[OFF_SOFT + node] = expf(sc) / denom;
}

// PDL launch helper: dependent blocks spin up during the predecessor's tail.
template <typename F, typename... Args>
static void launch_pdl(F f, dim3 grid, dim3 block, Args... args) {
    cudaLaunchConfig_t cfg = {};
    cfg.gridDim = grid;
    cfg.blockDim = block;
    cfg.stream = 0;
    cudaLaunchAttribute at[1];
    at[0].id = cudaLaunchAttributeProgrammaticStreamSerialization;
    at[0].val.programmaticStreamSerializationAllowed = 1;
    cfg.attrs = at;
    cfg.numAttrs = 1;
    cudaLaunchKernelEx(&cfg, f, args...);
}

extern "C" void kernel_launch(void* const* d_in, const int* in_sizes, int n_in,
                              void* d_out, int out_size) {
    const float* feat = (const float*)d_in[0];
    const float* W    = (const float*)d_in[1];
    const float* b    = (const float*)d_in[2];
    const int*   src  = (const int*)d_in[3];
    const int*   dst  = (const int*)d_in[4];
    float* out = (float*)d_out;
    (void)in_sizes; (void)n_in; (void)out_size;

    launch_pdl(k_xw_deg, dim3(16000), dim3(256), feat, W, src);
    launch_pdl(k_h, dim3(NT / 256), dim3(256));
    launch_pdl(k_agg, dim3(EE / 16 / 256), dim3(256), src, dst);
    launch_pdl(k_topk, dim3(BB), dim3(512), b, out);
    launch_pdl(k_final, dim3(8000), dim3(512), feat, src, dst, out);
}